// round 1
// baseline (speedup 1.0000x reference)
#include <cuda_runtime.h>
#include <cuda_bf16.h>

// Problem shapes (fixed):
//   x_main: [1, T=128, M=512, K=256] fp32
//   x_aux : [K=256, T=128, Da=256]   fp32
//   W     : [Da=256, E=512]          fp32
//   b     : [E=512]                  fp32
//   out   : [1, T, M, E, 1] = [128, 512, 512] fp32
//
// Stage 1: aux_out[k,t,e] = relu(sum_d x_aux[k,t,d]*W[d,e] + b[e])
//          computed as GEMM  A1[32768,256] x W[256,512], row r = k*128 + t,
//          scattered into scratch[t][k][e]  (so stage-2 B tiles are row-major).
// Stage 2: out[t,m,e] = sum_k x_main[t,m,k] * scratch[t][k][e]
//          128 batched GEMMs of [512,256] x [256,512].

__device__ float g_scratch[128 * 256 * 512];  // [T][K][E], 64 MB

constexpr int TK  = 16;    // K tile
constexpr int TM  = 128;   // M tile
constexpr int TN  = 128;   // N tile
constexpr int ALD = TM + 4; // padded lead dim for As (kills STS bank conflicts)

template <bool STAGE1>
__global__ __launch_bounds__(256, 2) void slam_gemm_kernel(
    const float* __restrict__ A_,   // stage1: x_aux flat [32768,256]; stage2: x_main [T][512][256]
    const float* __restrict__ B_,   // stage1: W [256,512]; stage2: unused (g_scratch)
    const float* __restrict__ bias, // stage1: b[512]; stage2: unused
    float* __restrict__ C_)         // stage2: out [T][512][512]; stage1: unused (g_scratch)
{
    __shared__ __align__(16) float As[2][TK][ALD];  // As[buf][kk][m]
    __shared__ __align__(16) float Bs[2][TK][TN];   // Bs[buf][kk][n]

    const int tid = threadIdx.x;
    const int tx  = tid & 15;   // n-direction, owns 8 consecutive n
    const int ty  = tid >> 4;   // m-direction, owns 8 consecutive m
    const int n0  = blockIdx.x * TN;
    const int m0  = blockIdx.y * TM;

    const float* A;
    const float* B;
    float*       C;
    if (STAGE1) {
        A = A_;
        B = B_;
        C = nullptr;
    } else {
        const int t = blockIdx.z;
        A = A_ + (size_t)t * (512 * 256);
        B = g_scratch + (size_t)t * (256 * 512);
        C = C_ + (size_t)t * (512 * 512);
    }

    // Global-load mapping: 256 threads, 2 float4 each per operand tile.
    // A tile: TM x TK  -> 512 float4.  row = tid>>2 (+64), col4 = tid&3
    // B tile: TK x TN  -> 512 float4.  row = tid>>5 (+8),  col4 = tid&31
    const int rowA = tid >> 2, c4A = tid & 3;
    const int rowB = tid >> 5, c4B = tid & 31;

    const float* Aptr = A + (size_t)(m0 + rowA) * 256 + c4A * 4;
    const float* Bptr = B + (size_t)rowB * 512 + n0 + c4B * 4;

    float4 av0, av1, bv0, bv1;

    auto ldg_tile = [&](int kb) {
        av0 = *reinterpret_cast<const float4*>(Aptr + kb);
        av1 = *reinterpret_cast<const float4*>(Aptr + kb + (size_t)64 * 256);
        bv0 = *reinterpret_cast<const float4*>(Bptr + (size_t)kb * 512);
        bv1 = *reinterpret_cast<const float4*>(Bptr + (size_t)(kb + 8) * 512);
    };

    auto sts_tile = [&](int nb) {
        As[nb][c4A * 4 + 0][rowA]      = av0.x;
        As[nb][c4A * 4 + 1][rowA]      = av0.y;
        As[nb][c4A * 4 + 2][rowA]      = av0.z;
        As[nb][c4A * 4 + 3][rowA]      = av0.w;
        As[nb][c4A * 4 + 0][rowA + 64] = av1.x;
        As[nb][c4A * 4 + 1][rowA + 64] = av1.y;
        As[nb][c4A * 4 + 2][rowA + 64] = av1.z;
        As[nb][c4A * 4 + 3][rowA + 64] = av1.w;
        *reinterpret_cast<float4*>(&Bs[nb][rowB][c4B * 4])     = bv0;
        *reinterpret_cast<float4*>(&Bs[nb][rowB + 8][c4B * 4]) = bv1;
    };

    float acc[8][8];
#pragma unroll
    for (int i = 0; i < 8; ++i)
#pragma unroll
        for (int j = 0; j < 8; ++j) acc[i][j] = 0.0f;

    auto compute_tile = [&](int bf) {
#pragma unroll
        for (int kk = 0; kk < TK; ++kk) {
            const float4 a0 = *reinterpret_cast<const float4*>(&As[bf][kk][ty * 8]);
            const float4 a1 = *reinterpret_cast<const float4*>(&As[bf][kk][ty * 8 + 4]);
            const float4 b0 = *reinterpret_cast<const float4*>(&Bs[bf][kk][tx * 8]);
            const float4 b1 = *reinterpret_cast<const float4*>(&Bs[bf][kk][tx * 8 + 4]);
            const float a[8]  = {a0.x, a0.y, a0.z, a0.w, a1.x, a1.y, a1.z, a1.w};
            const float bb[8] = {b0.x, b0.y, b0.z, b0.w, b1.x, b1.y, b1.z, b1.w};
#pragma unroll
            for (int i = 0; i < 8; ++i)
#pragma unroll
                for (int j = 0; j < 8; ++j)
                    acc[i][j] = fmaf(a[i], bb[j], acc[i][j]);
        }
    };

    // Prologue: fill buffer 0
    ldg_tile(0);
    sts_tile(0);
    __syncthreads();

    int buf = 0;
#pragma unroll 1
    for (int kb = TK; kb < 256; kb += TK) {
        ldg_tile(kb);          // LDG into regs (overlaps with compute below)
        compute_tile(buf);
        sts_tile(buf ^ 1);
        __syncthreads();
        buf ^= 1;
    }
    compute_tile(buf);

    // Epilogue
    if (STAGE1) {
        float bias8[8];
#pragma unroll
        for (int j = 0; j < 8; ++j) bias8[j] = bias[n0 + tx * 8 + j];
#pragma unroll
        for (int i = 0; i < 8; ++i) {
            const int r  = m0 + ty * 8 + i;  // flat row = k*128 + t
            const int k_ = r >> 7;
            const int t_ = r & 127;
            float* Cp = g_scratch + (size_t)t_ * (256 * 512) + (size_t)k_ * 512 + n0 + tx * 8;
            float4 c0, c1;
            c0.x = fmaxf(acc[i][0] + bias8[0], 0.0f);
            c0.y = fmaxf(acc[i][1] + bias8[1], 0.0f);
            c0.z = fmaxf(acc[i][2] + bias8[2], 0.0f);
            c0.w = fmaxf(acc[i][3] + bias8[3], 0.0f);
            c1.x = fmaxf(acc[i][4] + bias8[4], 0.0f);
            c1.y = fmaxf(acc[i][5] + bias8[5], 0.0f);
            c1.z = fmaxf(acc[i][6] + bias8[6], 0.0f);
            c1.w = fmaxf(acc[i][7] + bias8[7], 0.0f);
            *reinterpret_cast<float4*>(Cp)     = c0;
            *reinterpret_cast<float4*>(Cp + 4) = c1;
        }
    } else {
#pragma unroll
        for (int i = 0; i < 8; ++i) {
            float* Cp = C + (size_t)(m0 + ty * 8 + i) * 512 + n0 + tx * 8;
            *reinterpret_cast<float4*>(Cp) =
                make_float4(acc[i][0], acc[i][1], acc[i][2], acc[i][3]);
            *reinterpret_cast<float4*>(Cp + 4) =
                make_float4(acc[i][4], acc[i][5], acc[i][6], acc[i][7]);
        }
    }
}

extern "C" void kernel_launch(void* const* d_in, const int* in_sizes, int n_in,
                              void* d_out, int out_size) {
    const float* x_main = (const float*)d_in[0];  // [1,128,512,256]
    const float* x_aux  = (const float*)d_in[1];  // [256,128,256]
    const float* W      = (const float*)d_in[2];  // [256,512]
    const float* b      = (const float*)d_in[3];  // [512]
    float* out = (float*)d_out;                   // [1,128,512,512,1]

    // Stage 1: 32768 x 512 x 256 GEMM + bias + relu -> g_scratch [T][K][E]
    slam_gemm_kernel<true><<<dim3(4, 256, 1), 256>>>(x_aux, W, b, nullptr);
    // Stage 2: 128 batched 512 x 512 x 256 GEMMs -> out
    slam_gemm_kernel<false><<<dim3(4, 4, 128), 256>>>(x_main, nullptr, nullptr, out);
}

// round 3
// speedup vs baseline: 2.6835x; 2.6835x over previous
#include <cuda_runtime.h>
#include <cstdint>

// Shapes (fixed):
//   x_main: [1, T=128, M=512, K=256] fp32
//   x_aux : [K=256, T=128, Da=256]   fp32
//   W     : [Da=256, E=512]          fp32
//   b     : [E=512]                  fp32
//   out   : [1,T,M,E,1] = [128,512,512] fp32
//
// Stage 1 (per t): scratch[t][e][k] = relu( sum_d W[d][e]*x_aux[k][t][d] + b[e] )
//   GEMM M=e(512), N=k(256), red=d.  A-op = W (kept [d][e] in smem, transposed at
//   fragment load), B-op = x_aux k-rows (K-major).  Bias indexed by M-row, relu.
// Stage 2 (per t): out[t][m][e] = sum_k x_main[t][m][k] * scratch[t][e][k]
//   GEMM M=m(512), N=e(512), red=k.  A = x_main[t] (row-major), B = scratch[t] (K-major).
//
// mma.sync.m16n8k8 tf32 (baseline PTX -- tcgen05 is not available on this
// toolchain's sm_103 target).  CTA 128x128xBK32, 8 warps (2m x 4n), warp 64x32.

__device__ float g_scratch[128 * 512 * 256];  // [T][E][K], 64 MB

static constexpr int BM = 128, BN = 128, BK = 32;
static constexpr int LDA = 36;    // [128 rows][32 k] pad->36  (banks 4g+tg: conflict-free)
static constexpr int LDB = 36;
static constexpr int LDW = 136;   // W tile [32 d][128 e] pad->136 (banks 8tg+g: conflict-free)
static constexpr int A_TILE_B = BM * LDA * 4;        // 18432 (>= 32*136*4 = 17408 W tile)
static constexpr int B_TILE_B = BN * LDB * 4;        // 18432
static constexpr int SMEM_TOTAL = 2 * (A_TILE_B + B_TILE_B);  // 73728 -> 2 CTAs/SM

__device__ __forceinline__ uint32_t smem_u32(const void* p) {
    uint32_t a;
    asm("{ .reg .u64 t; cvta.to.shared.u64 t, %1; cvt.u32.u64 %0, t; }" : "=r"(a) : "l"(p));
    return a;
}
__device__ __forceinline__ uint32_t f2tf32(float f) {
    uint32_t r;
    asm("cvt.rna.tf32.f32 %0, %1;" : "=r"(r) : "f"(f));
    return r;
}
#define CP_ASYNC16(dst32, src) \
    asm volatile("cp.async.cg.shared.global [%0], [%1], 16;" :: "r"(dst32), "l"(src))
#define CP_COMMIT() asm volatile("cp.async.commit_group;" ::: "memory")
#define CP_WAIT0()  asm volatile("cp.async.wait_group 0;" ::: "memory")

__device__ __forceinline__ void mma_tf32(float* d, const uint32_t* a, const uint32_t* b) {
    asm volatile(
        "mma.sync.aligned.m16n8k8.row.col.f32.tf32.tf32.f32 "
        "{%0,%1,%2,%3}, {%4,%5,%6,%7}, {%8,%9}, {%0,%1,%2,%3};"
        : "+f"(d[0]), "+f"(d[1]), "+f"(d[2]), "+f"(d[3])
        : "r"(a[0]), "r"(a[1]), "r"(a[2]), "r"(a[3]), "r"(b[0]), "r"(b[1]));
}

template <bool STAGE1>
__global__ void __launch_bounds__(256, 2)
slam_mma_kernel(const float* __restrict__ Aglob, const float* __restrict__ Bglob,
                const float* __restrict__ bias, float* __restrict__ Cglob) {
    extern __shared__ __align__(16) char smem[];
    const uint32_t sb = smem_u32(smem);
    const int tid = threadIdx.x;
    const int wid = tid >> 5;
    const int lid = tid & 31;
    const int g  = lid >> 2;   // groupID
    const int tg = lid & 3;    // thread-in-group
    const int warp_m = (wid & 1) * 64;
    const int warp_n = (wid >> 1) * 32;
    const int t  = blockIdx.z;
    const int m0 = blockIdx.y * BM;
    const int n0 = blockIdx.x * BN;

    const float* A;  // stage1: W [256][512]; stage2: x_main[t] [512][256]
    const float* B;  // stage1: x_aux k-rows (stride 32768); stage2: scratch[t] [512][256]
    float* C;
    size_t b_rstride;
    if (STAGE1) {
        A = Aglob;                                 // W
        B = Bglob + (size_t)t * 256;               // x_aux[.,t,.]
        C = g_scratch + (size_t)t * 512 * 256;     // [e][k]
        b_rstride = 128 * 256;
    } else {
        A = Aglob + (size_t)t * 512 * 256;
        B = g_scratch + (size_t)t * 512 * 256;
        C = Cglob + (size_t)t * 512 * 512;
        b_rstride = 256;
    }

    const uint32_t aoff[2] = {sb, sb + A_TILE_B};
    const uint32_t boff[2] = {sb + 2 * A_TILE_B, sb + 2 * A_TILE_B + B_TILE_B};

    auto load_tile = [&](int kt, int buf) {
        // ---- A tile ----
        if (STAGE1) {
            // W tile [32 d][128 e], natural layout, ld=136 floats (544 B rows)
#pragma unroll
            for (int i = 0; i < 4; ++i) {
                const int idx = tid + i * 256;   // 0..1023
                const int row = idx >> 5;        // d 0..31
                const int ch  = idx & 31;        // 16B chunk along e
                CP_ASYNC16(aoff[buf] + row * 544 + ch * 16,
                           A + (size_t)(kt * 32 + row) * 512 + m0 + ch * 4);
            }
        } else {
            // x_main tile [128 m][32 k], ld=36 floats (144 B rows)
#pragma unroll
            for (int i = 0; i < 4; ++i) {
                const int idx = tid + i * 256;
                const int row = idx >> 3;        // m 0..127
                const int ch  = idx & 7;
                CP_ASYNC16(aoff[buf] + row * 144 + ch * 16,
                           A + (size_t)(m0 + row) * 256 + kt * 32 + ch * 4);
            }
        }
        // ---- B tile [128 n][32 k], ld=36 ----
#pragma unroll
        for (int i = 0; i < 4; ++i) {
            const int idx = tid + i * 256;
            const int row = idx >> 3;
            const int ch  = idx & 7;
            CP_ASYNC16(boff[buf] + row * 144 + ch * 16,
                       B + (size_t)(n0 + row) * b_rstride + kt * 32 + ch * 4);
        }
    };

    float acc[4][4][4];
#pragma unroll
    for (int mi = 0; mi < 4; ++mi)
#pragma unroll
        for (int nj = 0; nj < 4; ++nj)
#pragma unroll
            for (int q = 0; q < 4; ++q) acc[mi][nj][q] = 0.0f;

    auto compute_tile = [&](int buf) {
        const float* As = (const float*)(smem + (buf ? A_TILE_B : 0));
        const float* Bs = (const float*)(smem + 2 * A_TILE_B + (buf ? B_TILE_B : 0));
#pragma unroll
        for (int ks = 0; ks < 4; ++ks) {
            const int k8 = ks * 8;
            uint32_t af[4][4], bf[4][2];
#pragma unroll
            for (int mi = 0; mi < 4; ++mi) {
                if (STAGE1) {
                    // A frag (row m=e, col k=d) from W-layout smem [d][e]
                    const int e_ = warp_m + 16 * mi + g;
                    const int d_ = k8 + tg;
                    af[mi][0] = f2tf32(As[d_ * LDW + e_]);
                    af[mi][1] = f2tf32(As[d_ * LDW + e_ + 8]);
                    af[mi][2] = f2tf32(As[(d_ + 4) * LDW + e_]);
                    af[mi][3] = f2tf32(As[(d_ + 4) * LDW + e_ + 8]);
                } else {
                    const int r_ = warp_m + 16 * mi + g;
                    const int c_ = k8 + tg;
                    af[mi][0] = f2tf32(As[r_ * LDA + c_]);
                    af[mi][1] = f2tf32(As[(r_ + 8) * LDA + c_]);
                    af[mi][2] = f2tf32(As[r_ * LDA + c_ + 4]);
                    af[mi][3] = f2tf32(As[(r_ + 8) * LDA + c_ + 4]);
                }
            }
#pragma unroll
            for (int nj = 0; nj < 4; ++nj) {
                const int n_ = warp_n + 8 * nj + g;   // b: col n = groupID
                bf[nj][0] = f2tf32(Bs[n_ * LDB + k8 + tg]);
                bf[nj][1] = f2tf32(Bs[n_ * LDB + k8 + tg + 4]);
            }
#pragma unroll
            for (int mi = 0; mi < 4; ++mi)
#pragma unroll
                for (int nj = 0; nj < 4; ++nj)
                    mma_tf32(acc[mi][nj], af[mi], bf[nj]);
        }
    };

    // ---- pipelined mainloop: 8 k-tiles of 32, double-buffered cp.async ----
    load_tile(0, 0);
    CP_COMMIT();
    int buf = 0;
#pragma unroll 1
    for (int kt = 0; kt < 8; ++kt) {
        CP_WAIT0();
        __syncthreads();
        if (kt < 7) {
            load_tile(kt + 1, buf ^ 1);
            CP_COMMIT();
        }
        compute_tile(buf);
        __syncthreads();
        buf ^= 1;
    }

    // ---- epilogue ----
    const int cld = STAGE1 ? 256 : 512;   // C row stride (N extent)
#pragma unroll
    for (int mi = 0; mi < 4; ++mi) {
        const int r0 = m0 + warp_m + 16 * mi + g;
        const int r1 = r0 + 8;
        float bv0 = 0.0f, bv1 = 0.0f;
        if (STAGE1) { bv0 = bias[r0]; bv1 = bias[r1]; }
#pragma unroll
        for (int nj = 0; nj < 4; ++nj) {
            const int col = n0 + warp_n + 8 * nj + 2 * tg;
            float2 v0, v1;
            v0.x = acc[mi][nj][0]; v0.y = acc[mi][nj][1];
            v1.x = acc[mi][nj][2]; v1.y = acc[mi][nj][3];
            if (STAGE1) {
                v0.x = fmaxf(v0.x + bv0, 0.0f); v0.y = fmaxf(v0.y + bv0, 0.0f);
                v1.x = fmaxf(v1.x + bv1, 0.0f); v1.y = fmaxf(v1.y + bv1, 0.0f);
            }
            *reinterpret_cast<float2*>(C + (size_t)r0 * cld + col) = v0;
            *reinterpret_cast<float2*>(C + (size_t)r1 * cld + col) = v1;
        }
    }
}

extern "C" void kernel_launch(void* const* d_in, const int* in_sizes, int n_in,
                              void* d_out, int out_size) {
    const float* x_main = (const float*)d_in[0];  // [1,128,512,256]
    const float* x_aux  = (const float*)d_in[1];  // [256,128,256]
    const float* W      = (const float*)d_in[2];  // [256,512]
    const float* b      = (const float*)d_in[3];  // [512]
    float* out = (float*)d_out;                   // [128,512,512]

    cudaFuncSetAttribute(slam_mma_kernel<true>,
                         cudaFuncAttributeMaxDynamicSharedMemorySize, SMEM_TOTAL);
    cudaFuncSetAttribute(slam_mma_kernel<false>,
                         cudaFuncAttributeMaxDynamicSharedMemorySize, SMEM_TOTAL);

    // Stage 1: per-t  D[e(512) x k(256)] = W^T x_aux[.,t,.]^T (+bias, relu) -> scratch
    slam_mma_kernel<true><<<dim3(2, 4, 128), 256, SMEM_TOTAL>>>(W, x_aux, b, nullptr);
    // Stage 2: per-t  D[m(512) x e(512)] = x_main[t] . scratch[t]^T -> out
    slam_mma_kernel<false><<<dim3(4, 4, 128), 256, SMEM_TOTAL>>>(x_main, nullptr, nullptr, out);
}

// round 4
// speedup vs baseline: 2.8556x; 1.0641x over previous
#include <cuda_runtime.h>
#include <cstdint>

// Shapes (fixed):
//   x_main: [1, T=128, M=512, K=256] fp32
//   x_aux : [K=256, T=128, Da=256]   fp32
//   W     : [Da=256, E=512]          fp32
//   b     : [E=512]                  fp32
//   out   : [1,T,M,E,1] = [128,512,512] fp32
//
// Stage 1 (per t): scratch[t][e][k] = relu( sum_d W[d][e]*x_aux[k][t][d] + b[e] )
//   M=e(512), N=k(256), red=d.  A-op = W (pre-rounded tf32, natural [d][e] smem
//   layout, transposed at fragment gather), B-op = x_aux rows (LDG+cvt+STS).
// Stage 2 (per t): out[t][m][e] = sum_k x_main[t][m][k] * scratch[t][e][k]
//   M=m(512), N=e(512), red=k.  A = x_main (LDG+cvt+STS), B = scratch
//   (pre-rounded tf32 by stage-1 epilogue, cp.async).
//
// All operands are rna-rounded to tf32 exactly once => numerics identical to R3.
// Inner loop is pure LDS + mma.sync.m16n8k8 (no cvt on the critical path).

__device__ float g_scratch[128 * 512 * 256];  // [T][E][K], 64 MB (tf32-rounded)
__device__ float g_Wtf32[256 * 512];          // W pre-rounded to tf32

static constexpr int BM = 128, BN = 128;
static constexpr int LDT = 36;    // [128 rows][32 k] pad->36  (banks 4g+tg: conflict-free)
static constexpr int LDW = 136;   // W tile [32 d][128 e] pad->136 (banks 8tg+g: conflict-free)
static constexpr int A_TILE_B = BM * LDT * 4;        // 18432 (>= 32*136*4 = 17408 W tile)
static constexpr int B_TILE_B = BN * LDT * 4;        // 18432
static constexpr int SMEM_TOTAL = 2 * (A_TILE_B + B_TILE_B);  // 73728 -> 2 CTAs/SM

__device__ __forceinline__ uint32_t smem_u32(const void* p) {
    uint32_t a;
    asm("{ .reg .u64 t; cvta.to.shared.u64 t, %1; cvt.u32.u64 %0, t; }" : "=r"(a) : "l"(p));
    return a;
}
__device__ __forceinline__ float f2tf32f(float f) {
    uint32_t r;
    asm("cvt.rna.tf32.f32 %0, %1;" : "=r"(r) : "f"(f));
    return __uint_as_float(r);
}
#define CP_ASYNC16(dst32, src) \
    asm volatile("cp.async.cg.shared.global [%0], [%1], 16;" :: "r"(dst32), "l"(src))
#define CP_COMMIT() asm volatile("cp.async.commit_group;" ::: "memory")
#define CP_WAIT0()  asm volatile("cp.async.wait_group 0;" ::: "memory")

__device__ __forceinline__ void mma_tf32(float* d, const uint32_t* a, const uint32_t* b) {
    asm volatile(
        "mma.sync.aligned.m16n8k8.row.col.f32.tf32.tf32.f32 "
        "{%0,%1,%2,%3}, {%4,%5,%6,%7}, {%8,%9}, {%0,%1,%2,%3};"
        : "+f"(d[0]), "+f"(d[1]), "+f"(d[2]), "+f"(d[3])
        : "r"(a[0]), "r"(a[1]), "r"(a[2]), "r"(a[3]), "r"(b[0]), "r"(b[1]));
}

// Pre-pass: round W to tf32 once (512 KB, ~2us)
__global__ void w_round_kernel(const float* __restrict__ W) {
    const int i = blockIdx.x * 256 + threadIdx.x;   // 32768 float4
    float4 v = reinterpret_cast<const float4*>(W)[i];
    v.x = f2tf32f(v.x); v.y = f2tf32f(v.y); v.z = f2tf32f(v.z); v.w = f2tf32f(v.w);
    reinterpret_cast<float4*>(g_Wtf32)[i] = v;
}

template <bool STAGE1>
__global__ void __launch_bounds__(256, 2)
slam_mma_kernel(const float* __restrict__ Aglob, const float* __restrict__ Bglob,
                const float* __restrict__ bias, float* __restrict__ Cglob) {
    extern __shared__ __align__(16) char smem[];
    const uint32_t sb = smem_u32(smem);
    const int tid = threadIdx.x;
    const int wid = tid >> 5;
    const int lid = tid & 31;
    const int g  = lid >> 2;   // groupID
    const int tg = lid & 3;    // thread-in-group
    const int warp_m = (wid & 1) * 64;
    const int warp_n = (wid >> 1) * 32;
    const int t  = blockIdx.z;
    const int m0 = blockIdx.y * BM;
    const int n0 = blockIdx.x * BN;

    // cp.async operand: stage1 -> A tile (W, pre-rounded); stage2 -> B tile (scratch)
    // ldg-staged operand: stage1 -> B tile (x_aux);        stage2 -> A tile (x_main)
    const float* cp_src;    size_t cp_rstride;   // row-major [row][...] source
    const float* ld_src;    size_t ld_rstride;
    float* C;
    if (STAGE1) {
        cp_src = g_Wtf32;                           // [d][e], rows d
        cp_rstride = 512;
        ld_src = Bglob + (size_t)t * 256;           // x_aux[.,t,.], rows k, stride 32768
        ld_rstride = 128 * 256;
        C = g_scratch + (size_t)t * 512 * 256;      // [e][k]
    } else {
        ld_src = Aglob + (size_t)t * 512 * 256;     // x_main[t], rows m
        ld_rstride = 256;
        cp_src = g_scratch + (size_t)t * 512 * 256; // rows e
        cp_rstride = 256;
        C = Cglob + (size_t)t * 512 * 512;
    }

    const uint32_t aoff[2] = {sb, sb + A_TILE_B};
    const uint32_t boff[2] = {sb + 2 * A_TILE_B, sb + 2 * A_TILE_B + B_TILE_B};

    // ---- cp.async tile (no conversion needed: data pre-rounded) ----
    auto cpasync_tile = [&](int kt, int buf) {
        if (STAGE1) {
            // W tile [32 d][128 e], ld=136 floats (544 B rows)
#pragma unroll
            for (int i = 0; i < 4; ++i) {
                const int idx = tid + i * 256;   // 0..1023
                const int row = idx >> 5;        // d 0..31
                const int ch  = idx & 31;        // 16B chunk along e
                CP_ASYNC16(aoff[buf] + row * 544 + ch * 16,
                           cp_src + (size_t)(kt * 32 + row) * cp_rstride + m0 + ch * 4);
            }
        } else {
            // scratch tile [128 e][32 k], ld=36 floats (144 B rows)
#pragma unroll
            for (int i = 0; i < 4; ++i) {
                const int idx = tid + i * 256;
                const int row = idx >> 3;        // e 0..127
                const int ch  = idx & 7;
                CP_ASYNC16(boff[buf] + row * 144 + ch * 16,
                           cp_src + (size_t)(n0 + row) * cp_rstride + kt * 32 + ch * 4);
            }
        }
    };

    // ---- register-staged LDG of the other operand ----
    const int srow = tid >> 3;        // 0..127 (m or k row)
    const int sch  = tid & 7;         // float4 chunk along reduction dim
    auto ldg_tile = [&](int kt, float4 (&r)[4]) {
        const int base_row = STAGE1 ? n0 : m0;
#pragma unroll
        for (int i = 0; i < 4; ++i)
            r[i] = *reinterpret_cast<const float4*>(
                ld_src + (size_t)(base_row + srow + i * 32) * ld_rstride
                       + kt * 32 + sch * 4);
    };
    auto sts_tile = [&](float4 (&r)[4], int buf) {
        const uint32_t base = (STAGE1 ? boff[buf] : aoff[buf]) + srow * 144 + sch * 16;
#pragma unroll
        for (int i = 0; i < 4; ++i) {
            float4 v = r[i];
            v.x = f2tf32f(v.x); v.y = f2tf32f(v.y);
            v.z = f2tf32f(v.z); v.w = f2tf32f(v.w);
            *reinterpret_cast<float4*>((char*)nullptr + base + i * 32 * 144) = v;
        }
    };

    float acc[4][4][4];
#pragma unroll
    for (int mi = 0; mi < 4; ++mi)
#pragma unroll
        for (int nj = 0; nj < 4; ++nj)
#pragma unroll
            for (int q = 0; q < 4; ++q) acc[mi][nj][q] = 0.0f;

    auto compute_tile = [&](int buf) {
        const float* As = (const float*)(smem + (buf ? A_TILE_B : 0));
        const float* Bs = (const float*)(smem + 2 * A_TILE_B + (buf ? B_TILE_B : 0));
#pragma unroll
        for (int ks = 0; ks < 4; ++ks) {
            const int k8 = ks * 8;
            uint32_t af[4][4], bf[4][2];
#pragma unroll
            for (int mi = 0; mi < 4; ++mi) {
                if (STAGE1) {
                    // A frag (row m=e, col k=d) from W-layout smem [d][e]
                    const int e_ = warp_m + 16 * mi + g;
                    const int d_ = k8 + tg;
                    af[mi][0] = __float_as_uint(As[d_ * LDW + e_]);
                    af[mi][1] = __float_as_uint(As[d_ * LDW + e_ + 8]);
                    af[mi][2] = __float_as_uint(As[(d_ + 4) * LDW + e_]);
                    af[mi][3] = __float_as_uint(As[(d_ + 4) * LDW + e_ + 8]);
                } else {
                    const int r_ = warp_m + 16 * mi + g;
                    const int c_ = k8 + tg;
                    af[mi][0] = __float_as_uint(As[r_ * LDT + c_]);
                    af[mi][1] = __float_as_uint(As[(r_ + 8) * LDT + c_]);
                    af[mi][2] = __float_as_uint(As[r_ * LDT + c_ + 4]);
                    af[mi][3] = __float_as_uint(As[(r_ + 8) * LDT + c_ + 4]);
                }
            }
#pragma unroll
            for (int nj = 0; nj < 4; ++nj) {
                const int n_ = warp_n + 8 * nj + g;
                bf[nj][0] = __float_as_uint(Bs[n_ * LDT + k8 + tg]);
                bf[nj][1] = __float_as_uint(Bs[n_ * LDT + k8 + tg + 4]);
            }
#pragma unroll
            for (int mi = 0; mi < 4; ++mi)
#pragma unroll
                for (int nj = 0; nj < 4; ++nj)
                    mma_tf32(acc[mi][nj], af[mi], bf[nj]);
        }
    };

    // ---- pipelined mainloop: 8 k-tiles of 32, double-buffered ----
    float4 stage_regs[4];
    cpasync_tile(0, 0);
    CP_COMMIT();
    ldg_tile(0, stage_regs);
    CP_WAIT0();
    {   // STS needs smem byte address; rebuild base via sb-relative store
        const uint32_t base = (STAGE1 ? boff[0] : aoff[0]) + srow * 144 + sch * 16;
#pragma unroll
        for (int i = 0; i < 4; ++i) {
            float4 v = stage_regs[i];
            v.x = f2tf32f(v.x); v.y = f2tf32f(v.y);
            v.z = f2tf32f(v.z); v.w = f2tf32f(v.w);
            asm volatile("st.shared.v4.b32 [%0], {%1,%2,%3,%4};"
                         :: "r"(base + i * 32 * 144),
                            "f"(v.x), "f"(v.y), "f"(v.z), "f"(v.w) : "memory");
        }
    }
    __syncthreads();

    int buf = 0;
#pragma unroll 1
    for (int kt = 0; kt < 8; ++kt) {
        if (kt < 7) {
            cpasync_tile(kt + 1, buf ^ 1);
            CP_COMMIT();
            ldg_tile(kt + 1, stage_regs);
        }
        compute_tile(buf);
        if (kt < 7) {
            CP_WAIT0();
            const uint32_t base =
                (STAGE1 ? boff[buf ^ 1] : aoff[buf ^ 1]) + srow * 144 + sch * 16;
#pragma unroll
            for (int i = 0; i < 4; ++i) {
                float4 v = stage_regs[i];
                v.x = f2tf32f(v.x); v.y = f2tf32f(v.y);
                v.z = f2tf32f(v.z); v.w = f2tf32f(v.w);
                asm volatile("st.shared.v4.b32 [%0], {%1,%2,%3,%4};"
                             :: "r"(base + i * 32 * 144),
                                "f"(v.x), "f"(v.y), "f"(v.z), "f"(v.w) : "memory");
            }
            __syncthreads();
        }
        buf ^= 1;
    }

    // ---- epilogue ----
    const int cld = STAGE1 ? 256 : 512;
#pragma unroll
    for (int mi = 0; mi < 4; ++mi) {
        const int r0 = m0 + warp_m + 16 * mi + g;
        const int r1 = r0 + 8;
        float bv0 = 0.0f, bv1 = 0.0f;
        if (STAGE1) { bv0 = bias[r0]; bv1 = bias[r1]; }
#pragma unroll
        for (int nj = 0; nj < 4; ++nj) {
            const int col = n0 + warp_n + 8 * nj + 2 * tg;
            float2 v0, v1;
            v0.x = acc[mi][nj][0]; v0.y = acc[mi][nj][1];
            v1.x = acc[mi][nj][2]; v1.y = acc[mi][nj][3];
            if (STAGE1) {
                // bias + relu, then pre-round for stage-2's MMA (numerics == R3)
                v0.x = f2tf32f(fmaxf(v0.x + bv0, 0.0f));
                v0.y = f2tf32f(fmaxf(v0.y + bv0, 0.0f));
                v1.x = f2tf32f(fmaxf(v1.x + bv1, 0.0f));
                v1.y = f2tf32f(fmaxf(v1.y + bv1, 0.0f));
            }
            *reinterpret_cast<float2*>(C + (size_t)r0 * cld + col) = v0;
            *reinterpret_cast<float2*>(C + (size_t)r1 * cld + col) = v1;
        }
    }
}

extern "C" void kernel_launch(void* const* d_in, const int* in_sizes, int n_in,
                              void* d_out, int out_size) {
    const float* x_main = (const float*)d_in[0];  // [1,128,512,256]
    const float* x_aux  = (const float*)d_in[1];  // [256,128,256]
    const float* W      = (const float*)d_in[2];  // [256,512]
    const float* b      = (const float*)d_in[3];  // [512]
    float* out = (float*)d_out;                   // [128,512,512]

    cudaFuncSetAttribute(slam_mma_kernel<true>,
                         cudaFuncAttributeMaxDynamicSharedMemorySize, SMEM_TOTAL);
    cudaFuncSetAttribute(slam_mma_kernel<false>,
                         cudaFuncAttributeMaxDynamicSharedMemorySize, SMEM_TOTAL);

    // Pre-round W to tf32 (once per launch; cheap)
    w_round_kernel<<<128, 256>>>(W);
    // Stage 1: per-t  D[e(512) x k(256)] = W^T x_aux[.,t,.]^T (+bias, relu) -> scratch
    slam_mma_kernel<true><<<dim3(2, 4, 128), 256, SMEM_TOTAL>>>(nullptr, x_aux, b, nullptr);
    // Stage 2: per-t  D[m(512) x e(512)] = x_main[t] . scratch[t]^T -> out
    slam_mma_kernel<false><<<dim3(4, 4, 128), 256, SMEM_TOTAL>>>(x_main, nullptr, nullptr, out);
}